// round 4
// baseline (speedup 1.0000x reference)
#include <cuda_runtime.h>
#include <math.h>

#define B_      64
#define P_      56
#define N_      3136
#define DIM_    256
#define HEADS_  4
#define HD_     24
#define HH_     96
#define M_      16
#define OUT_    256
#define NT_     (B_*N_)        // 200704
#define BH_     (B_*HEADS_)    // 256

typedef unsigned long long u64;

// ---------------- scratch (device globals; no allocation) ----------------
__device__ float g_xbar[B_*M_*DIM_];                   // pooled x       [B,16,256]
__device__ float g_centhat[BH_*M_*HD_];                // normalized feat centers
__device__ float g_vcent[BH_*M_*HD_];                  // value centers
__device__ float g_s[BH_*N_];                          // chosen sim value per (bh,n)
__device__ unsigned char g_a[BH_*N_];                  // argmax center per (bh,n)
__device__ float g_xs_part[4*B_*HEADS_*M_*DIM_];       // partial s-weighted x sums (16 MB)
__device__ float g_cnt_part[4*B_*HEADS_*M_];
__device__ float g_ssum_part[4*B_*HEADS_*M_];
__device__ float g_pa[BH_*M_*OUT_];                    // proj_w @ agg   [bh,16,256]

// ---------------- K1: pool raw x into xbar (block = (b,m)) ----------------
__global__ __launch_bounds__(256) void k_pool(const float* __restrict__ x) {
    int b = blockIdx.x >> 4, m = blockIdx.x & 15;
    int pw = m >> 2, ph = m & 3;
    int c = threadIdx.x;
    const float* xb = x + (size_t)b * N_ * DIM_;
    float s = 0.f;
    #pragma unroll 2
    for (int wi = 0; wi < 14; wi++) {
        int w = pw*14 + wi;
        #pragma unroll 2
        for (int hi = 0; hi < 14; hi++) {
            int n = w*P_ + ph*14 + hi;
            s += xb[(size_t)n*DIM_ + c];
        }
    }
    g_xbar[(b*M_ + m)*DIM_ + c] = s * (1.f/196.f);
}

// ---------------- K2: centers from xbar (block = (b,m)) ----------------
__global__ __launch_bounds__(256) void k_cent(const float* __restrict__ fw, const float* __restrict__ fb,
                                              const float* __restrict__ vw, const float* __restrict__ vb) {
    __shared__ float xb[DIM_];
    __shared__ float cf_sh[HH_];
    int b = blockIdx.x >> 4, m = blockIdx.x & 15;
    xb[threadIdx.x] = g_xbar[(b*M_ + m)*DIM_ + threadIdx.x];
    __syncthreads();
    int j = threadIdx.x;
    if (j < HH_) {
        float cf = fb[j], cv = vb[j];
        const float* fwr = fw + (size_t)j*DIM_;
        const float* vwr = vw + (size_t)j*DIM_;
        #pragma unroll 8
        for (int k = 0; k < DIM_; k++) { cf += fwr[k]*xb[k]; cv += vwr[k]*xb[k]; }
        cf_sh[j] = cf;
        int head = j / HD_, d = j % HD_;
        g_vcent[((b*HEADS_ + head)*M_ + m)*HD_ + d] = cv;
    }
    __syncthreads();
    if (j < HH_) {
        int head = j / HD_, d = j % HD_;
        float ss = 0.f;
        #pragma unroll
        for (int dd = 0; dd < HD_; dd++) { float v = cf_sh[head*HD_ + dd]; ss += v*v; }
        float inv = 1.f / fmaxf(sqrtf(ss), 1e-12f);
        g_centhat[((b*HEADS_ + head)*M_ + m)*HD_ + d] = cf_sh[j] * inv;
    }
}

// ---------------- K3: fused feat GEMM (FFMA2 + reg-staged double buffer) + sim/argmax ----
// BM=128, BN=96, BK=32, 256 threads. 8x6 register tile held as 4x6 packed f32x2
// row-pairs; mainloop uses fma.rn.f32x2 (SASS FFMA2). Next tile's LDG.128s are
// issued before the compute phase so their latency overlaps the 32-step loop.
__global__ __launch_bounds__(256) void k_featsim(const float* __restrict__ x,
                                                 const float* __restrict__ fw,
                                                 const float* __restrict__ fb,
                                                 const float* __restrict__ sa,
                                                 const float* __restrict__ sb) {
    __shared__ __align__(16) float As[32][130];   // [k][row], row-pairs 8B aligned
    __shared__ __align__(16) float Bs[32][98];    // [k][col]
    __shared__ float cent[2][HEADS_*M_*HD_];      // centers for the (up to) 2 batches spanned
    const int t0 = blockIdx.x * 128;
    const int tid = threadIdx.x;
    const int tx = tid & 15, ty = tid >> 4;

    const int b0 = t0 / N_;
    const int b1 = min(b0 + 1, B_ - 1);
    const int bsplit = (b0 + 1) * N_;

    for (int i = tid; i < 2*HEADS_*M_*HD_; i += 256) {
        int set = i / (HEADS_*M_*HD_);
        int idx = i - set*(HEADS_*M_*HD_);
        int bb = set ? b1 : b0;
        cent[set][idx] = g_centhat[(size_t)bb*(HEADS_*M_*HD_) + idx];
    }

    u64 acc2[4][6];
    #pragma unroll
    for (int i = 0; i < 4; i++)
        #pragma unroll
        for (int j = 0; j < 6; j++) acc2[i][j] = 0ull;   // (0.f, 0.f)

    const float4* x4 = (const float4*)x;
    const float4* w4 = (const float4*)fw;

    // per-thread load coordinates (fixed across tiles)
    const int lrA = tid >> 3;               // A row this thread loads (with +128,+256,+384 offsets via p? no: idx-based)
    // NOTE: loads below use idx = tid + p*256 pattern; precompute nothing else.

    float4 ra[4], rb[3];
    // prologue: load tile k0=0 into registers
    #pragma unroll
    for (int p = 0; p < 4; p++) {
        int idx = tid + p*256; int r = idx >> 3, q = idx & 7;
        ra[p] = x4[(size_t)(t0 + r)*64 + q];
    }
    #pragma unroll
    for (int p = 0; p < 3; p++) {
        int idx = tid + p*256; int r = idx >> 3, q = idx & 7;
        rb[p] = w4[(size_t)r*64 + q];
    }

    for (int k0 = 0; k0 < DIM_; k0 += 32) {
        // store staged registers to smem (transposed)
        #pragma unroll
        for (int p = 0; p < 4; p++) {
            int idx = tid + p*256; int r = idx >> 3, q = idx & 7;
            As[4*q+0][r] = ra[p].x; As[4*q+1][r] = ra[p].y;
            As[4*q+2][r] = ra[p].z; As[4*q+3][r] = ra[p].w;
        }
        #pragma unroll
        for (int p = 0; p < 3; p++) {
            int idx = tid + p*256; int r = idx >> 3, q = idx & 7;
            Bs[4*q+0][r] = rb[p].x; Bs[4*q+1][r] = rb[p].y;
            Bs[4*q+2][r] = rb[p].z; Bs[4*q+3][r] = rb[p].w;
        }
        __syncthreads();

        // prefetch next tile (latency hidden behind compute below)
        if (k0 + 32 < DIM_) {
            int kq = (k0 + 32) >> 2;
            #pragma unroll
            for (int p = 0; p < 4; p++) {
                int idx = tid + p*256; int r = idx >> 3, q = idx & 7;
                ra[p] = x4[(size_t)(t0 + r)*64 + kq + q];
            }
            #pragma unroll
            for (int p = 0; p < 3; p++) {
                int idx = tid + p*256; int r = idx >> 3, q = idx & 7;
                rb[p] = w4[(size_t)r*64 + kq + q];
            }
        }

        #pragma unroll
        for (int kk = 0; kk < 32; kk++) {
            u64 a2[4];
            #pragma unroll
            for (int i = 0; i < 4; i++)
                a2[i] = *(const u64*)&As[kk][ty*8 + 2*i];      // LDS.64 row-pair
            u64 b2[6];
            #pragma unroll
            for (int j = 0; j < 6; j++) {
                float bv = Bs[kk][tx*6 + j];
                asm("mov.b64 %0, {%1, %1};" : "=l"(b2[j]) : "r"(__float_as_uint(bv)));
            }
            #pragma unroll
            for (int i = 0; i < 4; i++)
                #pragma unroll
                for (int j = 0; j < 6; j++)
                    asm("fma.rn.f32x2 %0, %1, %2, %0;" : "+l"(acc2[i][j]) : "l"(a2[i]), "l"(b2[j]));
        }
        __syncthreads();
    }

    // unpack packed accumulators -> accf[8][6]
    float accf[8][6];
    #pragma unroll
    for (int i = 0; i < 4; i++)
        #pragma unroll
        for (int j = 0; j < 6; j++) {
            unsigned lo, hi;
            asm("mov.b64 {%0, %1}, %2;" : "=r"(lo), "=r"(hi) : "l"(acc2[i][j]));
            accf[2*i][j]   = __uint_as_float(lo);
            accf[2*i+1][j] = __uint_as_float(hi);
        }

    // ---- epilogue: sim + argmax, no gmem feat traffic ----
    const float alpha = sa[0], beta = sb[0];
    const int g = tx >> 2;                // head
    const int off = (tx & 3) * 6;         // dim offset within head
    float fbv[6];
    #pragma unroll
    for (int j = 0; j < 6; j++) fbv[j] = fb[tx*6 + j];

    #pragma unroll
    for (int i = 0; i < 8; i++) {
        int tg = t0 + ty*8 + i;
        int bsel = (tg >= bsplit) ? 1 : 0;
        int b = b0 + bsel;

        float fv[6];
        float ss = 0.f;
        #pragma unroll
        for (int j = 0; j < 6; j++) { fv[j] = accf[i][j] + fbv[j]; ss += fv[j]*fv[j]; }

        float dot[M_];
        const float* cc = &cent[bsel][g*(M_*HD_) + off];
        #pragma unroll
        for (int m = 0; m < M_; m++) {
            float d = 0.f;
            #pragma unroll
            for (int j = 0; j < 6; j++) d += fv[j]*cc[m*HD_ + j];
            dot[m] = d;
        }
        // 4-lane butterfly reduction (lanes differ only in tx bits 0..1)
        #pragma unroll
        for (int dlt = 1; dlt <= 2; dlt <<= 1) {
            ss += __shfl_xor_sync(0xffffffff, ss, dlt);
            #pragma unroll
            for (int m = 0; m < M_; m++) dot[m] += __shfl_xor_sync(0xffffffff, dot[m], dlt);
        }
        float inv = 1.f / fmaxf(sqrtf(ss), 1e-12f);
        float best = -INFINITY; int bi = 0;
        #pragma unroll
        for (int m = 0; m < M_; m++) {
            float z = beta + alpha*(dot[m]*inv);
            z = (z > 0.f) ? z : 0.2f*z;
            if (z > best) { best = z; bi = m; }
        }
        if ((tx & 3) == 0) {
            int gi = (b*HEADS_ + g)*N_ + (tg - b*N_);
            g_s[gi] = best;
            g_a[gi] = (unsigned char)bi;
        }
    }
}

// ---------------- K5: s-weighted x sums per (bh,m); warp-owned centers, no atomics ----
__global__ __launch_bounds__(256) void k_xs(const float* __restrict__ x) {
    __shared__ float sx[32][DIM_];
    __shared__ float ssv[HEADS_][32];
    __shared__ unsigned char sav[HEADS_][32];
    int q = blockIdx.x & 3, b = blockIdx.x >> 2;
    int n0 = q * 784;
    int tid = threadIdx.x, w = tid >> 5, lane = tid & 31;

    float acc0[4][8], acc1[4][8];
    float cnt0[4], cnt1[4], s0[4], s1[4];
    #pragma unroll
    for (int h = 0; h < 4; h++) {
        cnt0[h] = cnt1[h] = s0[h] = s1[h] = 0.f;
        #pragma unroll
        for (int k = 0; k < 8; k++) { acc0[h][k] = 0.f; acc1[h][k] = 0.f; }
    }

    for (int c0 = 0; c0 < 784; c0 += 32) {
        int ct = min(32, 784 - c0);
        __syncthreads();
        const float4* x4 = (const float4*)(x + ((size_t)b*N_ + n0 + c0)*DIM_);
        for (int idx = tid; idx < ct*64; idx += 256) {
            int t = idx >> 6, c = idx & 63;
            ((float4*)sx[t])[c] = x4[(size_t)t*64 + c];
        }
        for (int i = tid; i < HEADS_*32; i += 256) {
            int h = i >> 5, t = i & 31;
            if (t < ct) {
                int gi = (b*HEADS_ + h)*N_ + n0 + c0 + t;
                ssv[h][t] = g_s[gi];
                sav[h][t] = g_a[gi];
            }
        }
        __syncthreads();
        for (int t = 0; t < ct; t++) {
            #pragma unroll
            for (int h = 0; h < 4; h++) {
                int a = sav[h][t];
                if ((a >> 1) == w) {
                    float s = ssv[h][t];
                    if (a & 1) {
                        #pragma unroll
                        for (int k = 0; k < 8; k++) acc1[h][k] += s * sx[t][lane + 32*k];
                        cnt1[h] += 1.f; s1[h] += s;
                    } else {
                        #pragma unroll
                        for (int k = 0; k < 8; k++) acc0[h][k] += s * sx[t][lane + 32*k];
                        cnt0[h] += 1.f; s0[h] += s;
                    }
                }
            }
        }
    }
    #pragma unroll
    for (int h = 0; h < 4; h++) {
        size_t base = (size_t)(((q*B_ + b)*HEADS_ + h)*M_ + 2*w) * DIM_;
        #pragma unroll
        for (int k = 0; k < 8; k++) g_xs_part[base + lane + 32*k] = acc0[h][k];
        #pragma unroll
        for (int k = 0; k < 8; k++) g_xs_part[base + DIM_ + lane + 32*k] = acc1[h][k];
        if (lane == 0) {
            int mi = ((q*B_ + b)*HEADS_ + h)*M_ + 2*w;
            g_cnt_part[mi]     = cnt0[h]; g_cnt_part[mi + 1]  = cnt1[h];
            g_ssum_part[mi]    = s0[h];   g_ssum_part[mi + 1] = s1[h];
        }
    }
}

// ---------------- K6: finalize agg + precompute PA (block = (bh,m)) ----------------
__global__ __launch_bounds__(256) void k_vagg(const float* __restrict__ vw, const float* __restrict__ vb,
                                              const float* __restrict__ pw) {
    __shared__ float sx[DIM_];
    __shared__ float part[24][8];
    __shared__ float aggv[HD_];
    __shared__ float meta[2];
    int m = blockIdx.x & 15, bh = blockIdx.x >> 4;
    int b = bh >> 2, h = bh & 3;
    int tid = threadIdx.x;
    {
        float v = 0.f;
        #pragma unroll
        for (int q = 0; q < 4; q++)
            v += g_xs_part[(size_t)(((q*B_ + b)*HEADS_ + h)*M_ + m)*DIM_ + tid];
        sx[tid] = v;
    }
    if (tid == 0) {
        float c = 0.f, s = 0.f;
        #pragma unroll
        for (int q = 0; q < 4; q++) {
            int mi = ((q*B_ + b)*HEADS_ + h)*M_ + m;
            c += g_cnt_part[mi]; s += g_ssum_part[mi];
        }
        meta[0] = c; meta[1] = s;
    }
    __syncthreads();
    if (tid < 192) {
        int d = tid >> 3, r = tid & 7;
        const float* vwr = vw + (size_t)(h*HD_ + d)*DIM_;
        float p = 0.f;
        for (int c = r; c < DIM_; c += 8) p += vwr[c]*sx[c];
        part[d][r] = p;
    }
    __syncthreads();
    if (tid < HD_) {
        float dot = 0.f;
        #pragma unroll
        for (int r = 0; r < 8; r++) dot += part[tid][r];
        float val = (dot + meta[1]*vb[h*HD_ + tid] + g_vcent[(bh*M_ + m)*HD_ + tid]) / (meta[0] + 1.f);
        aggv[tid] = val;
    }
    __syncthreads();
    {
        int o = tid;
        const float* pwr = pw + (size_t)o*HH_ + h*HD_;
        float pa = 0.f;
        #pragma unroll
        for (int d = 0; d < HD_; d++) pa += pwr[d]*aggv[d];
        g_pa[(size_t)(bh*M_ + m)*OUT_ + o] = pa;
    }
}

// ---------------- K7: dispatch + projection (4 FMAs / output element) ----------------
__global__ __launch_bounds__(256) void k_out(const float* __restrict__ pb, float* __restrict__ out) {
    int w = threadIdx.x >> 5, lane = threadIdx.x & 31;
    int tg = blockIdx.x*8 + w;              // global token id, 0..NT-1 (exact)
    int b = tg / N_, n = tg % N_;
    int o0 = lane * 8;
    const float4* pb4 = (const float4*)pb;
    float4 r0 = pb4[o0 >> 2], r1 = pb4[(o0 >> 2) + 1];
    #pragma unroll
    for (int h = 0; h < 4; h++) {
        int gi = (b*HEADS_ + h)*N_ + n;
        float s = g_s[gi];
        int a = g_a[gi];
        const float4* pap = (const float4*)(g_pa + (size_t)((b*HEADS_ + h)*M_ + a)*OUT_ + o0);
        float4 p0 = pap[0], p1 = pap[1];
        r0.x += s*p0.x; r0.y += s*p0.y; r0.z += s*p0.z; r0.w += s*p0.w;
        r1.x += s*p1.x; r1.y += s*p1.y; r1.z += s*p1.z; r1.w += s*p1.w;
    }
    float4* o4 = (float4*)(out + (size_t)tg*OUT_ + o0);
    o4[0] = r0; o4[1] = r1;
}

// ---------------- launch ----------------
extern "C" void kernel_launch(void* const* d_in, const int* in_sizes, int n_in,
                              void* d_out, int out_size) {
    const float* x  = (const float*)d_in[0];
    const float* fw = (const float*)d_in[1];
    const float* fb = (const float*)d_in[2];
    const float* vw = (const float*)d_in[3];
    const float* vb = (const float*)d_in[4];
    const float* pw = (const float*)d_in[5];
    const float* pb = (const float*)d_in[6];
    const float* sa = (const float*)d_in[7];
    const float* sb = (const float*)d_in[8];
    float* out = (float*)d_out;

    k_pool<<<B_*M_, 256>>>(x);
    k_cent<<<B_*M_, 256>>>(fw, fb, vw, vb);
    k_featsim<<<NT_/128, 256>>>(x, fw, fb, sa, sb);
    k_xs<<<B_*4, 256>>>(x);
    k_vagg<<<BH_*M_, 256>>>(vw, vb, pw);
    k_out<<<NT_/8, 256>>>(pb, out);
}

// round 7
// speedup vs baseline: 1.1164x; 1.1164x over previous
#include <cuda_runtime.h>
#include <math.h>

#define B_      64
#define P_      56
#define N_      3136
#define DIM_    256
#define HEADS_  4
#define HD_     24
#define HH_     96
#define M_      16
#define OUT_    256
#define NT_     (B_*N_)        // 200704
#define BH_     (B_*HEADS_)    // 256
#define NQ_     7              // token chunks per batch for k_xs
#define TQ_     (N_/NQ_)       // 448
#define CH_     16             // tokens per smem chunk in k_xs
#define NCH_    (TQ_/CH_)      // 28

typedef unsigned long long u64;

// ---------------- scratch (device globals; no allocation) ----------------
__device__ float g_xbar[B_*M_*DIM_];                   // pooled x       [B,16,256]
__device__ float g_centhat[BH_*M_*HD_];                // normalized feat centers
__device__ float g_vcent[BH_*M_*HD_];                  // value centers
__device__ float g_sv[(size_t)NT_*4];                  // sim value per (token, head) interleaved
__device__ unsigned char g_av4[(size_t)NT_*4];         // argmax center per (token, head) interleaved
__device__ float g_xs_part[NQ_*B_*HEADS_*M_*DIM_];     // partial s-weighted x sums (28 MB)
__device__ float g_cnt_part[NQ_*B_*HEADS_*M_];
__device__ float g_ssum_part[NQ_*B_*HEADS_*M_];
__device__ float g_pa[BH_*M_*OUT_];                    // proj_w @ agg   [bh,16,256]
__device__ float g_warm;

// ---------------- K1: pool raw x into xbar (block = (b,m)) ----------------
// NOTE: summation order is part of the argmax contract (R4 bits). DO NOT reorder.
__global__ __launch_bounds__(256) void k_pool(const float* __restrict__ x) {
    int b = blockIdx.x >> 4, m = blockIdx.x & 15;
    int pw = m >> 2, ph = m & 3;
    int c = threadIdx.x;
    const float* xb = x + (size_t)b * N_ * DIM_;
    float s = 0.f;
    #pragma unroll 2
    for (int wi = 0; wi < 14; wi++) {
        int w = pw*14 + wi;
        #pragma unroll 2
        for (int hi = 0; hi < 14; hi++) {
            int n = w*P_ + ph*14 + hi;
            s += xb[(size_t)n*DIM_ + c];
        }
    }
    g_xbar[(b*M_ + m)*DIM_ + c] = s * (1.f/196.f);
}

// ---------------- K2: centers from xbar (block = (b,m)) ----------------
__global__ __launch_bounds__(256) void k_cent(const float* __restrict__ fw, const float* __restrict__ fb,
                                              const float* __restrict__ vw, const float* __restrict__ vb) {
    __shared__ float xb[DIM_];
    __shared__ float cf_sh[HH_];
    int b = blockIdx.x >> 4, m = blockIdx.x & 15;
    xb[threadIdx.x] = g_xbar[(b*M_ + m)*DIM_ + threadIdx.x];
    __syncthreads();
    int j = threadIdx.x;
    if (j < HH_) {
        float cf = fb[j], cv = vb[j];
        const float* fwr = fw + (size_t)j*DIM_;
        const float* vwr = vw + (size_t)j*DIM_;
        #pragma unroll 8
        for (int k = 0; k < DIM_; k++) { cf += fwr[k]*xb[k]; cv += vwr[k]*xb[k]; }
        cf_sh[j] = cf;
        int head = j / HD_, d = j % HD_;
        g_vcent[((b*HEADS_ + head)*M_ + m)*HD_ + d] = cv;
    }
    __syncthreads();
    if (j < HH_) {
        int head = j / HD_, d = j % HD_;
        float ss = 0.f;
        #pragma unroll
        for (int dd = 0; dd < HD_; dd++) { float v = cf_sh[head*HD_ + dd]; ss += v*v; }
        float inv = 1.f / fmaxf(sqrtf(ss), 1e-12f);
        g_centhat[((b*HEADS_ + head)*M_ + m)*HD_ + d] = cf_sh[j] * inv;
    }
}

// ---------------- tiny kernel to rotate the ncu capture slot onto k_featsim ----
__global__ void k_warm() { if (threadIdx.x == 0) g_warm = 1.f; }

// ---------------- K3: fused feat GEMM (FFMA2 + reg-staged double buffer) + sim/argmax ----
// Pre-argmax numerics: identical to the R4 passing kernel. DO NOT reorder math here.
__global__ __launch_bounds__(256) void k_featsim(const float* __restrict__ x,
                                                 const float* __restrict__ fw,
                                                 const float* __restrict__ fb,
                                                 const float* __restrict__ sa,
                                                 const float* __restrict__ sb) {
    __shared__ __align__(16) float As[32][130];   // [k][row], row-pairs 8B aligned
    __shared__ __align__(16) float Bs[32][98];    // [k][col]
    __shared__ float cent[2][HEADS_*M_*HD_];      // centers for the (up to) 2 batches spanned
    const int t0 = blockIdx.x * 128;
    const int tid = threadIdx.x;
    const int tx = tid & 15, ty = tid >> 4;

    const int b0 = t0 / N_;
    const int b1 = min(b0 + 1, B_ - 1);
    const int bsplit = (b0 + 1) * N_;

    for (int i = tid; i < 2*HEADS_*M_*HD_; i += 256) {
        int set = i / (HEADS_*M_*HD_);
        int idx = i - set*(HEADS_*M_*HD_);
        int bb = set ? b1 : b0;
        cent[set][idx] = g_centhat[(size_t)bb*(HEADS_*M_*HD_) + idx];
    }

    u64 acc2[4][6];
    #pragma unroll
    for (int i = 0; i < 4; i++)
        #pragma unroll
        for (int j = 0; j < 6; j++) acc2[i][j] = 0ull;

    const float4* x4 = (const float4*)x;
    const float4* w4 = (const float4*)fw;

    float4 ra[4], rb[3];
    #pragma unroll
    for (int p = 0; p < 4; p++) {
        int idx = tid + p*256; int r = idx >> 3, q = idx & 7;
        ra[p] = x4[(size_t)(t0 + r)*64 + q];
    }
    #pragma unroll
    for (int p = 0; p < 3; p++) {
        int idx = tid + p*256; int r = idx >> 3, q = idx & 7;
        rb[p] = w4[(size_t)r*64 + q];
    }

    for (int k0 = 0; k0 < DIM_; k0 += 32) {
        #pragma unroll
        for (int p = 0; p < 4; p++) {
            int idx = tid + p*256; int r = idx >> 3, q = idx & 7;
            As[4*q+0][r] = ra[p].x; As[4*q+1][r] = ra[p].y;
            As[4*q+2][r] = ra[p].z; As[4*q+3][r] = ra[p].w;
        }
        #pragma unroll
        for (int p = 0; p < 3; p++) {
            int idx = tid + p*256; int r = idx >> 3, q = idx & 7;
            Bs[4*q+0][r] = rb[p].x; Bs[4*q+1][r] = rb[p].y;
            Bs[4*q+2][r] = rb[p].z; Bs[4*q+3][r] = rb[p].w;
        }
        __syncthreads();

        if (k0 + 32 < DIM_) {
            int kq = (k0 + 32) >> 2;
            #pragma unroll
            for (int p = 0; p < 4; p++) {
                int idx = tid + p*256; int r = idx >> 3, q = idx & 7;
                ra[p] = x4[(size_t)(t0 + r)*64 + kq + q];
            }
            #pragma unroll
            for (int p = 0; p < 3; p++) {
                int idx = tid + p*256; int r = idx >> 3, q = idx & 7;
                rb[p] = w4[(size_t)r*64 + kq + q];
            }
        }

        #pragma unroll
        for (int kk = 0; kk < 32; kk++) {
            u64 a2[4];
            #pragma unroll
            for (int i = 0; i < 4; i++)
                a2[i] = *(const u64*)&As[kk][ty*8 + 2*i];
            u64 b2[6];
            #pragma unroll
            for (int j = 0; j < 6; j++) {
                float bv = Bs[kk][tx*6 + j];
                asm("mov.b64 %0, {%1, %1};" : "=l"(b2[j]) : "r"(__float_as_uint(bv)));
            }
            #pragma unroll
            for (int i = 0; i < 4; i++)
                #pragma unroll
                for (int j = 0; j < 6; j++)
                    asm("fma.rn.f32x2 %0, %1, %2, %0;" : "+l"(acc2[i][j]) : "l"(a2[i]), "l"(b2[j]));
        }
        __syncthreads();
    }

    float accf[8][6];
    #pragma unroll
    for (int i = 0; i < 4; i++)
        #pragma unroll
        for (int j = 0; j < 6; j++) {
            unsigned lo, hi;
            asm("mov.b64 {%0, %1}, %2;" : "=r"(lo), "=r"(hi) : "l"(acc2[i][j]));
            accf[2*i][j]   = __uint_as_float(lo);
            accf[2*i+1][j] = __uint_as_float(hi);
        }

    const float alpha = sa[0], beta = sb[0];
    const int g = tx >> 2;
    const int off = (tx & 3) * 6;
    float fbv[6];
    #pragma unroll
    for (int j = 0; j < 6; j++) fbv[j] = fb[tx*6 + j];

    #pragma unroll
    for (int i = 0; i < 8; i++) {
        int tg = t0 + ty*8 + i;
        int bsel = (tg >= bsplit) ? 1 : 0;

        float fv[6];
        float ss = 0.f;
        #pragma unroll
        for (int j = 0; j < 6; j++) { fv[j] = accf[i][j] + fbv[j]; ss += fv[j]*fv[j]; }

        float dot[M_];
        const float* cc = &cent[bsel][g*(M_*HD_) + off];
        #pragma unroll
        for (int m = 0; m < M_; m++) {
            float d = 0.f;
            #pragma unroll
            for (int j = 0; j < 6; j++) d += fv[j]*cc[m*HD_ + j];
            dot[m] = d;
        }
        #pragma unroll
        for (int dlt = 1; dlt <= 2; dlt <<= 1) {
            ss += __shfl_xor_sync(0xffffffff, ss, dlt);
            #pragma unroll
            for (int m = 0; m < M_; m++) dot[m] += __shfl_xor_sync(0xffffffff, dot[m], dlt);
        }
        float inv = 1.f / fmaxf(sqrtf(ss), 1e-12f);
        float best = -INFINITY; int bi = 0;
        #pragma unroll
        for (int m = 0; m < M_; m++) {
            float z = beta + alpha*(dot[m]*inv);
            z = (z > 0.f) ? z : 0.2f*z;
            if (z > best) { best = z; bi = m; }
        }
        if ((tx & 3) == 0) {
            g_sv[(size_t)tg*4 + g]  = best;
            g_av4[(size_t)tg*4 + g] = (unsigned char)bi;
        }
    }
}

// ---------------- K5: s-weighted x sums; warp-ballot matching + cp.async pipeline ----
#define XS_STAGE(c_) do { \
    const float* src_ = x + (tokbase + (size_t)(c_)*CH_)*DIM_; \
    _Pragma("unroll") \
    for (int r_ = 0; r_ < (CH_*DIM_/4)/256; r_++) { \
        int idx_ = tid + r_*256; int t_ = idx_ >> 6, col_ = idx_ & 63; \
        unsigned sa_ = (unsigned)__cvta_generic_to_shared(&sx[(c_) & 1][t_][col_*4]); \
        asm volatile("cp.async.cg.shared.global [%0], [%1], 16;" :: "r"(sa_), "l"(src_ + (size_t)t_*DIM_ + col_*4)); \
    } \
    asm volatile("cp.async.commit_group;"); \
} while (0)

__global__ __launch_bounds__(256) void k_xs(const float* __restrict__ x) {
    __shared__ __align__(16) float sx[2][CH_][DIM_];   // 32 KB double buffer
    int q = blockIdx.x % NQ_, b = blockIdx.x / NQ_;
    int tid = threadIdx.x, w = tid >> 5, lane = tid & 31;
    const size_t tokbase = (size_t)b*N_ + q*TQ_;

    float4 acc[4][2][2];
    float cnt[4][2], ssum[4][2];
    #pragma unroll
    for (int h = 0; h < 4; h++)
        #pragma unroll
        for (int c = 0; c < 2; c++) {
            cnt[h][c] = 0.f; ssum[h][c] = 0.f;
            acc[h][c][0] = make_float4(0.f,0.f,0.f,0.f);
            acc[h][c][1] = make_float4(0.f,0.f,0.f,0.f);
        }

    XS_STAGE(0);
    XS_STAGE(1);

    unsigned avn = 0xFFFFFFFFu; float4 svn = make_float4(0.f,0.f,0.f,0.f);
    if (lane < CH_) {
        size_t tok = tokbase + lane;
        avn = *(const unsigned*)(g_av4 + tok*4);
        svn = *(const float4*)(g_sv + tok*4);
    }

    for (int c = 0; c < NCH_; c++) {
        unsigned av = avn; float4 sv = svn;
        if (c + 1 < NCH_ && lane < CH_) {
            size_t tok = tokbase + (size_t)(c+1)*CH_ + lane;
            avn = *(const unsigned*)(g_av4 + tok*4);
            svn = *(const float4*)(g_sv + tok*4);
        }
        if (c + 1 < NCH_) asm volatile("cp.async.wait_group 1;");
        else              asm volatile("cp.async.wait_group 0;");
        __syncthreads();
        int buf = c & 1;
        #pragma unroll
        for (int h = 0; h < 4; h++) {
            float svh = (h==0)?sv.x:(h==1)?sv.y:(h==2)?sv.z:sv.w;
            int ah = (int)((av >> (8*h)) & 0xFFu);
            #pragma unroll
            for (int cc = 0; cc < 2; cc++) {
                unsigned mask = __ballot_sync(0xffffffffu, ah == 2*w + cc);
                cnt[h][cc] += (float)__popc(mask);
                while (mask) {
                    int t = __ffs(mask) - 1; mask &= mask - 1;
                    float s = __shfl_sync(0xffffffffu, svh, t);
                    ssum[h][cc] += s;
                    const float4* row = (const float4*)&sx[buf][t][lane << 3];
                    float4 v0 = row[0], v1 = row[1];
                    acc[h][cc][0].x += s*v0.x; acc[h][cc][0].y += s*v0.y;
                    acc[h][cc][0].z += s*v0.z; acc[h][cc][0].w += s*v0.w;
                    acc[h][cc][1].x += s*v1.x; acc[h][cc][1].y += s*v1.y;
                    acc[h][cc][1].z += s*v1.z; acc[h][cc][1].w += s*v1.w;
                }
            }
        }
        __syncthreads();
        if (c + 2 < NCH_) XS_STAGE(c + 2);
    }

    #pragma unroll
    for (int h = 0; h < 4; h++)
        #pragma unroll
        for (int cc = 0; cc < 2; cc++) {
            int m = 2*w + cc;
            size_t base = (size_t)(((q*B_ + b)*HEADS_ + h)*M_ + m)*DIM_ + (lane << 3);
            *(float4*)(g_xs_part + base)     = acc[h][cc][0];
            *(float4*)(g_xs_part + base + 4) = acc[h][cc][1];
            if (lane == 0) {
                int mi = ((q*B_ + b)*HEADS_ + h)*M_ + m;
                g_cnt_part[mi]  = cnt[h][cc];
                g_ssum_part[mi] = ssum[h][cc];
            }
        }
}

// ---------------- K6: finalize agg + precompute PA (block = (bh,m)) ----------------
__global__ __launch_bounds__(256) void k_vagg(const float* __restrict__ vw, const float* __restrict__ vb,
                                              const float* __restrict__ pw) {
    __shared__ float sx[DIM_];
    __shared__ float part[24][8];
    __shared__ float aggv[HD_];
    __shared__ float meta[2];
    int m = blockIdx.x & 15, bh = blockIdx.x >> 4;
    int b = bh >> 2, h = bh & 3;
    int tid = threadIdx.x;
    {
        float v = 0.f;
        #pragma unroll
        for (int q = 0; q < NQ_; q++)
            v += g_xs_part[(size_t)(((q*B_ + b)*HEADS_ + h)*M_ + m)*DIM_ + tid];
        sx[tid] = v;
    }
    if (tid == 0) {
        float c = 0.f, s = 0.f;
        #pragma unroll
        for (int q = 0; q < NQ_; q++) {
            int mi = ((q*B_ + b)*HEADS_ + h)*M_ + m;
            c += g_cnt_part[mi]; s += g_ssum_part[mi];
        }
        meta[0] = c; meta[1] = s;
    }
    __syncthreads();
    if (tid < 192) {
        int d = tid >> 3, r = tid & 7;
        const float* vwr = vw + (size_t)(h*HD_ + d)*DIM_;
        float p = 0.f;
        for (int c = r; c < DIM_; c += 8) p += vwr[c]*sx[c];
        part[d][r] = p;
    }
    __syncthreads();
    if (tid < HD_) {
        float dot = 0.f;
        #pragma unroll
        for (int r = 0; r < 8; r++) dot += part[tid][r];
        float val = (dot + meta[1]*vb[h*HD_ + tid] + g_vcent[(bh*M_ + m)*HD_ + tid]) / (meta[0] + 1.f);
        aggv[tid] = val;
    }
    __syncthreads();
    {
        int o = tid;
        const float* pwr = pw + (size_t)o*HH_ + h*HD_;
        float pa = 0.f;
        #pragma unroll
        for (int d = 0; d < HD_; d++) pa += pwr[d]*aggv[d];
        g_pa[(size_t)(bh*M_ + m)*OUT_ + o] = pa;
    }
}

// ---------------- K7: dispatch + projection (4 FMAs / output element) ----------------
__global__ __launch_bounds__(256) void k_out(const float* __restrict__ pb, float* __restrict__ out) {
    int w = threadIdx.x >> 5, lane = threadIdx.x & 31;
    int tg = blockIdx.x*8 + w;
    int b = tg / N_;
    int o0 = lane * 8;
    float4 sv = *(const float4*)(g_sv + (size_t)tg*4);
    unsigned av = *(const unsigned*)(g_av4 + (size_t)tg*4);
    const float4* pb4 = (const float4*)pb;
    float4 r0 = pb4[o0 >> 2], r1 = pb4[(o0 >> 2) + 1];
    #pragma unroll
    for (int h = 0; h < 4; h++) {
        float s = (h==0)?sv.x:(h==1)?sv.y:(h==2)?sv.z:sv.w;
        int a = (int)((av >> (8*h)) & 0xFFu);
        const float4* pap = (const float4*)(g_pa + (size_t)((b*HEADS_ + h)*M_ + a)*OUT_ + o0);
        float4 p0 = pap[0], p1 = pap[1];
        r0.x += s*p0.x; r0.y += s*p0.y; r0.z += s*p0.z; r0.w += s*p0.w;
        r1.x += s*p1.x; r1.y += s*p1.y; r1.z += s*p1.z; r1.w += s*p1.w;
    }
    float4* o4 = (float4*)(out + (size_t)tg*OUT_ + o0);
    o4[0] = r0; o4[1] = r1;
}

// ---------------- launch ----------------
extern "C" void kernel_launch(void* const* d_in, const int* in_sizes, int n_in,
                              void* d_out, int out_size) {
    const float* x  = (const float*)d_in[0];
    const float* fw = (const float*)d_in[1];
    const float* fb = (const float*)d_in[2];
    const float* vw = (const float*)d_in[3];
    const float* vb = (const float*)d_in[4];
    const float* pw = (const float*)d_in[5];
    const float* pb = (const float*)d_in[6];
    const float* sa = (const float*)d_in[7];
    const float* sb = (const float*)d_in[8];
    float* out = (float*)d_out;

    k_pool<<<B_*M_, 256>>>(x);
    k_cent<<<B_*M_, 256>>>(fw, fb, vw, vb);
    k_warm<<<1, 32>>>();
    k_featsim<<<NT_/128, 256>>>(x, fw, fb, sa, sb);
    k_xs<<<B_*NQ_, 256>>>(x);
    k_vagg<<<BH_*M_, 256>>>(vw, vb, pw);
    k_out<<<NT_/8, 256>>>(pb, out);
}

// round 13
// speedup vs baseline: 1.1183x; 1.0017x over previous
#include <cuda_runtime.h>
#include <math.h>

#define B_      64
#define P_      56
#define N_      3136
#define DIM_    256
#define HEADS_  4
#define HD_     24
#define HH_     96
#define M_      16
#define OUT_    256
#define NT_     (B_*N_)        // 200704
#define BH_     (B_*HEADS_)    // 256
#define NQ_     7              // token chunks per batch for k_xs
#define TQ_     (N_/NQ_)       // 448
#define CH_     16             // tokens per smem chunk in k_xs
#define NCH_    (TQ_/CH_)      // 28

typedef unsigned long long u64;

// ---------------- scratch (device globals; no allocation) ----------------
__device__ float g_xbar[B_*M_*DIM_];                   // pooled x       [B,16,256]
__device__ float g_centhat[BH_*M_*HD_];                // normalized feat centers
__device__ float g_vcent[BH_*M_*HD_];                  // value centers
__device__ float g_sv[(size_t)NT_*4];                  // sim value per (token, head) interleaved
__device__ unsigned char g_av4[(size_t)NT_*4];         // argmax center per (token, head) interleaved
__device__ float g_xs_part[NQ_*B_*HEADS_*M_*DIM_];     // partial s-weighted x sums (28 MB)
__device__ float g_cnt_part[NQ_*B_*HEADS_*M_];
__device__ float g_ssum_part[NQ_*B_*HEADS_*M_];
__device__ float g_pa[BH_*M_*OUT_];                    // proj_w @ agg   [bh,16,256]
__device__ float g_warm;

// ---------------- K1: pool raw x into xbar (block = (b,m)) ----------------
// NOTE: FP summation ORDER is part of the argmax contract (R4 bits): adds go
// wi=0..13, hi=0..13 strictly in order. Loads are hoisted per-row for MLP=14,
// which does not change the addition order or any bit of the result.
__global__ __launch_bounds__(256) void k_pool(const float* __restrict__ x) {
    int b = blockIdx.x >> 4, m = blockIdx.x & 15;
    int pw = m >> 2, ph = m & 3;
    int c = threadIdx.x;
    const float* xb = x + (size_t)b * N_ * DIM_;
    float s = 0.f;
    #pragma unroll 1
    for (int wi = 0; wi < 14; wi++) {
        int w = pw*14 + wi;
        const float* rowp = xb + (size_t)(w*P_ + ph*14)*DIM_ + c;
        float v[14];
        #pragma unroll
        for (int hi = 0; hi < 14; hi++) v[hi] = rowp[(size_t)hi*DIM_];   // 14 independent LDGs
        #pragma unroll
        for (int hi = 0; hi < 14; hi++) s += v[hi];                      // original order
    }
    g_xbar[(b*M_ + m)*DIM_ + c] = s * (1.f/196.f);
}

// ---------------- K2: centers from xbar (block = (b,m)) ----------------
__global__ __launch_bounds__(256) void k_cent(const float* __restrict__ fw, const float* __restrict__ fb,
                                              const float* __restrict__ vw, const float* __restrict__ vb) {
    __shared__ float xb[DIM_];
    __shared__ float cf_sh[HH_];
    int b = blockIdx.x >> 4, m = blockIdx.x & 15;
    xb[threadIdx.x] = g_xbar[(b*M_ + m)*DIM_ + threadIdx.x];
    __syncthreads();
    int j = threadIdx.x;
    if (j < HH_) {
        float cf = fb[j], cv = vb[j];
        const float* fwr = fw + (size_t)j*DIM_;
        const float* vwr = vw + (size_t)j*DIM_;
        #pragma unroll 8
        for (int k = 0; k < DIM_; k++) { cf += fwr[k]*xb[k]; cv += vwr[k]*xb[k]; }
        cf_sh[j] = cf;
        int head = j / HD_, d = j % HD_;
        g_vcent[((b*HEADS_ + head)*M_ + m)*HD_ + d] = cv;
    }
    __syncthreads();
    if (j < HH_) {
        int head = j / HD_, d = j % HD_;
        float ss = 0.f;
        #pragma unroll
        for (int dd = 0; dd < HD_; dd++) { float v = cf_sh[head*HD_ + dd]; ss += v*v; }
        float inv = 1.f / fmaxf(sqrtf(ss), 1e-12f);
        g_centhat[((b*HEADS_ + head)*M_ + m)*HD_ + d] = cf_sh[j] * inv;
    }
}

// ---------------- tiny kernel to keep k_featsim in the ncu capture slot ----
__global__ void k_warm() { if (threadIdx.x == 0) g_warm = 1.f; }

// ---------------- K3: fused feat GEMM (FFMA2, wide LDS, reg double buffer) + sim/argmax ----
// Pre-argmax numerics: bit-identical accumulation order to R4/R7. DO NOT reorder math.
__global__ __launch_bounds__(256) void k_featsim(const float* __restrict__ x,
                                                 const float* __restrict__ fw,
                                                 const float* __restrict__ fb,
                                                 const float* __restrict__ sa,
                                                 const float* __restrict__ sb) {
    __shared__ __align__(16) float As[32][132];   // row = 528B (16B-aligned) for LDS.128
    __shared__ __align__(16) float Bs[32][98];    // row = 392B (8B-aligned) for LDS.64
    __shared__ float cent[2][HEADS_*M_*HD_];      // centers for the (up to) 2 batches spanned
    const int t0 = blockIdx.x * 128;
    const int tid = threadIdx.x;
    const int tx = tid & 15, ty = tid >> 4;

    const int b0 = t0 / N_;
    const int b1 = min(b0 + 1, B_ - 1);
    const int bsplit = (b0 + 1) * N_;

    for (int i = tid; i < 2*HEADS_*M_*HD_; i += 256) {
        int set = i / (HEADS_*M_*HD_);
        int idx = i - set*(HEADS_*M_*HD_);
        int bb = set ? b1 : b0;
        cent[set][idx] = g_centhat[(size_t)bb*(HEADS_*M_*HD_) + idx];
    }

    u64 acc2[4][6];
    #pragma unroll
    for (int i = 0; i < 4; i++)
        #pragma unroll
        for (int j = 0; j < 6; j++) acc2[i][j] = 0ull;

    const float4* x4 = (const float4*)x;
    const float4* w4 = (const float4*)fw;

    float4 ra[4], rb[3];
    #pragma unroll
    for (int p = 0; p < 4; p++) {
        int idx = tid + p*256; int r = idx >> 3, q = idx & 7;
        ra[p] = x4[(size_t)(t0 + r)*64 + q];
    }
    #pragma unroll
    for (int p = 0; p < 3; p++) {
        int idx = tid + p*256; int r = idx >> 3, q = idx & 7;
        rb[p] = w4[(size_t)r*64 + q];
    }

    for (int k0 = 0; k0 < DIM_; k0 += 32) {
        #pragma unroll
        for (int p = 0; p < 4; p++) {
            int idx = tid + p*256; int r = idx >> 3, q = idx & 7;
            As[4*q+0][r] = ra[p].x; As[4*q+1][r] = ra[p].y;
            As[4*q+2][r] = ra[p].z; As[4*q+3][r] = ra[p].w;
        }
        #pragma unroll
        for (int p = 0; p < 3; p++) {
            int idx = tid + p*256; int r = idx >> 3, q = idx & 7;
            Bs[4*q+0][r] = rb[p].x; Bs[4*q+1][r] = rb[p].y;
            Bs[4*q+2][r] = rb[p].z; Bs[4*q+3][r] = rb[p].w;
        }
        __syncthreads();

        if (k0 + 32 < DIM_) {
            int kq = (k0 + 32) >> 2;
            #pragma unroll
            for (int p = 0; p < 4; p++) {
                int idx = tid + p*256; int r = idx >> 3, q = idx & 7;
                ra[p] = x4[(size_t)(t0 + r)*64 + kq + q];
            }
            #pragma unroll
            for (int p = 0; p < 3; p++) {
                int idx = tid + p*256; int r = idx >> 3, q = idx & 7;
                rb[p] = w4[(size_t)r*64 + kq + q];
            }
        }

        #pragma unroll
        for (int kk = 0; kk < 32; kk++) {
            // A: 2x LDS.128 -> same row-pair u64s as before (bit-identical operands)
            ulonglong2 av0 = *(const ulonglong2*)&As[kk][ty*8];
            ulonglong2 av1 = *(const ulonglong2*)&As[kk][ty*8 + 4];
            u64 a2[4];
            a2[0] = av0.x; a2[1] = av0.y; a2[2] = av1.x; a2[3] = av1.y;
            // B: 3x LDS.64 column pairs, split + duplicate (same {b,b} values as before)
            u64 bp0 = *(const u64*)&Bs[kk][tx*6];
            u64 bp1 = *(const u64*)&Bs[kk][tx*6 + 2];
            u64 bp2 = *(const u64*)&Bs[kk][tx*6 + 4];
            u64 b2[6];
            {
                unsigned lo, hi;
                asm("mov.b64 {%0,%1}, %2;" : "=r"(lo), "=r"(hi) : "l"(bp0));
                asm("mov.b64 %0, {%1,%1};" : "=l"(b2[0]) : "r"(lo));
                asm("mov.b64 %0, {%1,%1};" : "=l"(b2[1]) : "r"(hi));
                asm("mov.b64 {%0,%1}, %2;" : "=r"(lo), "=r"(hi) : "l"(bp1));
                asm("mov.b64 %0, {%1,%1};" : "=l"(b2[2]) : "r"(lo));
                asm("mov.b64 %0, {%1,%1};" : "=l"(b2[3]) : "r"(hi));
                asm("mov.b64 {%0,%1}, %2;" : "=r"(lo), "=r"(hi) : "l"(bp2));
                asm("mov.b64 %0, {%1,%1};" : "=l"(b2[4]) : "r"(lo));
                asm("mov.b64 %0, {%1,%1};" : "=l"(b2[5]) : "r"(hi));
            }
            #pragma unroll
            for (int i = 0; i < 4; i++)
                #pragma unroll
                for (int j = 0; j < 6; j++)
                    asm("fma.rn.f32x2 %0, %1, %2, %0;" : "+l"(acc2[i][j]) : "l"(a2[i]), "l"(b2[j]));
        }
        __syncthreads();
    }

    float accf[8][6];
    #pragma unroll
    for (int i = 0; i < 4; i++)
        #pragma unroll
        for (int j = 0; j < 6; j++) {
            unsigned lo, hi;
            asm("mov.b64 {%0, %1}, %2;" : "=r"(lo), "=r"(hi) : "l"(acc2[i][j]));
            accf[2*i][j]   = __uint_as_float(lo);
            accf[2*i+1][j] = __uint_as_float(hi);
        }

    const float alpha = sa[0], beta = sb[0];
    const int g = tx >> 2;
    const int off = (tx & 3) * 6;
    float fbv[6];
    #pragma unroll
    for (int j = 0; j < 6; j++) fbv[j] = fb[tx*6 + j];

    #pragma unroll
    for (int i = 0; i < 8; i++) {
        int tg = t0 + ty*8 + i;
        int bsel = (tg >= bsplit) ? 1 : 0;

        float fv[6];
        float ss = 0.f;
        #pragma unroll
        for (int j = 0; j < 6; j++) { fv[j] = accf[i][j] + fbv[j]; ss += fv[j]*fv[j]; }

        float dot[M_];
        const float* cc = &cent[bsel][g*(M_*HD_) + off];
        #pragma unroll
        for (int m = 0; m < M_; m++) {
            float d = 0.f;
            #pragma unroll
            for (int j = 0; j < 6; j++) d += fv[j]*cc[m*HD_ + j];
            dot[m] = d;
        }
        #pragma unroll
        for (int dlt = 1; dlt <= 2; dlt <<= 1) {
            ss += __shfl_xor_sync(0xffffffff, ss, dlt);
            #pragma unroll
            for (int m = 0; m < M_; m++) dot[m] += __shfl_xor_sync(0xffffffff, dot[m], dlt);
        }
        float inv = 1.f / fmaxf(sqrtf(ss), 1e-12f);
        float best = -INFINITY; int bi = 0;
        #pragma unroll
        for (int m = 0; m < M_; m++) {
            float z = beta + alpha*(dot[m]*inv);
            z = (z > 0.f) ? z : 0.2f*z;
            if (z > best) { best = z; bi = m; }
        }
        if ((tx & 3) == 0) {
            g_sv[(size_t)tg*4 + g]  = best;
            g_av4[(size_t)tg*4 + g] = (unsigned char)bi;
        }
    }
}

// ---------------- K5: s-weighted x sums; warp-ballot matching + cp.async pipeline ----
#define XS_STAGE(c_) do { \
    const float* src_ = x + (tokbase + (size_t)(c_)*CH_)*DIM_; \
    _Pragma("unroll") \
    for (int r_ = 0; r_ < (CH_*DIM_/4)/256; r_++) { \
        int idx_ = tid + r_*256; int t_ = idx_ >> 6, col_ = idx_ & 63; \
        unsigned sa_ = (unsigned)__cvta_generic_to_shared(&sx[(c_) & 1][t_][col_*4]); \
        asm volatile("cp.async.cg.shared.global [%0], [%1], 16;" :: "r"(sa_), "l"(src_ + (size_t)t_*DIM_ + col_*4)); \
    } \
    asm volatile("cp.async.commit_group;"); \
} while (0)

__global__ __launch_bounds__(256) void k_xs(const float* __restrict__ x) {
    __shared__ __align__(16) float sx[2][CH_][DIM_];   // 32 KB double buffer
    int q = blockIdx.x % NQ_, b = blockIdx.x / NQ_;
    int tid = threadIdx.x, w = tid >> 5, lane = tid & 31;
    const size_t tokbase = (size_t)b*N_ + q*TQ_;

    float4 acc[4][2][2];
    float cnt[4][2], ssum[4][2];
    #pragma unroll
    for (int h = 0; h < 4; h++)
        #pragma unroll
        for (int c = 0; c < 2; c++) {
            cnt[h][c] = 0.f; ssum[h][c] = 0.f;
            acc[h][c][0] = make_float4(0.f,0.f,0.f,0.f);
            acc[h][c][1] = make_float4(0.f,0.f,0.f,0.f);
        }

    XS_STAGE(0);
    XS_STAGE(1);

    unsigned avn = 0xFFFFFFFFu; float4 svn = make_float4(0.f,0.f,0.f,0.f);
    if (lane < CH_) {
        size_t tok = tokbase + lane;
        avn = *(const unsigned*)(g_av4 + tok*4);
        svn = *(const float4*)(g_sv + tok*4);
    }

    for (int c = 0; c < NCH_; c++) {
        unsigned av = avn; float4 sv = svn;
        if (c + 1 < NCH_ && lane < CH_) {
            size_t tok = tokbase + (size_t)(c+1)*CH_ + lane;
            avn = *(const unsigned*)(g_av4 + tok*4);
            svn = *(const float4*)(g_sv + tok*4);
        }
        if (c + 1 < NCH_) asm volatile("cp.async.wait_group 1;");
        else              asm volatile("cp.async.wait_group 0;");
        __syncthreads();
        int buf = c & 1;
        #pragma unroll
        for (int h = 0; h < 4; h++) {
            float svh = (h==0)?sv.x:(h==1)?sv.y:(h==2)?sv.z:sv.w;
            int ah = (int)((av >> (8*h)) & 0xFFu);
            #pragma unroll
            for (int cc = 0; cc < 2; cc++) {
                unsigned mask = __ballot_sync(0xffffffffu, ah == 2*w + cc);
                cnt[h][cc] += (float)__popc(mask);
                while (mask) {
                    int t = __ffs(mask) - 1; mask &= mask - 1;
                    float s = __shfl_sync(0xffffffffu, svh, t);
                    ssum[h][cc] += s;
                    const float4* row = (const float4*)&sx[buf][t][lane << 3];
                    float4 v0 = row[0], v1 = row[1];
                    acc[h][cc][0].x += s*v0.x; acc[h][cc][0].y += s*v0.y;
                    acc[h][cc][0].z += s*v0.z; acc[h][cc][0].w += s*v0.w;
                    acc[h][cc][1].x += s*v1.x; acc[h][cc][1].y += s*v1.y;
                    acc[h][cc][1].z += s*v1.z; acc[h][cc][1].w += s*v1.w;
                }
            }
        }
        __syncthreads();
        if (c + 2 < NCH_) XS_STAGE(c + 2);
    }

    #pragma unroll
    for (int h = 0; h < 4; h++)
        #pragma unroll
        for (int cc = 0; cc < 2; cc++) {
            int m = 2*w + cc;
            size_t base = (size_t)(((q*B_ + b)*HEADS_ + h)*M_ + m)*DIM_ + (lane << 3);
            *(float4*)(g_xs_part + base)     = acc[h][cc][0];
            *(float4*)(g_xs_part + base + 4) = acc[h][cc][1];
            if (lane == 0) {
                int mi = ((q*B_ + b)*HEADS_ + h)*M_ + m;
                g_cnt_part[mi]  = cnt[h][cc];
                g_ssum_part[mi] = ssum[h][cc];
            }
        }
}

// ---------------- K6: finalize agg + precompute PA (block = (bh,m)) ----------------
__global__ __launch_bounds__(256) void k_vagg(const float* __restrict__ vw, const float* __restrict__ vb,
                                              const float* __restrict__ pw) {
    __shared__ float sx[DIM_];
    __shared__ float part[24][8];
    __shared__ float aggv[HD_];
    __shared__ float meta[2];
    int m = blockIdx.x & 15, bh = blockIdx.x >> 4;
    int b = bh >> 2, h = bh & 3;
    int tid = threadIdx.x;
    {
        float v = 0.f;
        #pragma unroll
        for (int q = 0; q < NQ_; q++)
            v += g_xs_part[(size_t)(((q*B_ + b)*HEADS_ + h)*M_ + m)*DIM_ + tid];
        sx[tid] = v;
    }
    if (tid == 0) {
        float c = 0.f, s = 0.f;
        #pragma unroll
        for (int q = 0; q < NQ_; q++) {
            int mi = ((q*B_ + b)*HEADS_ + h)*M_ + m;
            c += g_cnt_part[mi]; s += g_ssum_part[mi];
        }
        meta[0] = c; meta[1] = s;
    }
    __syncthreads();
    if (tid < 192) {
        int d = tid >> 3, r = tid & 7;
        const float* vwr = vw + (size_t)(h*HD_ + d)*DIM_;
        float p = 0.f;
        for (int c = r; c < DIM_; c += 8) p += vwr[c]*sx[c];
        part[d][r] = p;
    }
    __syncthreads();
    if (tid < HD_) {
        float dot = 0.f;
        #pragma unroll
        for (int r = 0; r < 8; r++) dot += part[tid][r];
        float val = (dot + meta[1]*vb[h*HD_ + tid] + g_vcent[(bh*M_ + m)*HD_ + tid]) / (meta[0] + 1.f);
        aggv[tid] = val;
    }
    __syncthreads();
    {
        int o = tid;
        const float* pwr = pw + (size_t)o*HH_ + h*HD_;
        float pa = 0.f;
        #pragma unroll
        for (int d = 0; d < HD_; d++) pa += pwr[d]*aggv[d];
        g_pa[(size_t)(bh*M_ + m)*OUT_ + o] = pa;
    }
}

// ---------------- K7: dispatch + projection (4 FMAs / output element) ----------------
__global__ __launch_bounds__(256) void k_out(const float* __restrict__ pb, float* __restrict__ out) {
    int w = threadIdx.x >> 5, lane = threadIdx.x & 31;
    int tg = blockIdx.x*8 + w;
    int b = tg / N_;
    int o0 = lane * 8;
    float4 sv = *(const float4*)(g_sv + (size_t)tg*4);
    unsigned av = *(const unsigned*)(g_av4 + (size_t)tg*4);
    const float4* pb4 = (const float4*)pb;
    float4 r0 = pb4[o0 >> 2], r1 = pb4[(o0 >> 2) + 1];
    #pragma unroll
    for (int h = 0; h < 4; h++) {
        float s = (h==0)?sv.x:(h==1)?sv.y:(h==2)?sv.z:sv.w;
        int a = (int)((av >> (8*h)) & 0xFFu);
        const float4* pap = (const float4*)(g_pa + (size_t)((b*HEADS_ + h)*M_ + a)*OUT_ + o0);
        float4 p0 = pap[0], p1 = pap[1];
        r0.x += s*p0.x; r0.y += s*p0.y; r0.z += s*p0.z; r0.w += s*p0.w;
        r1.x += s*p1.x; r1.y += s*p1.y; r1.z += s*p1.z; r1.w += s*p1.w;
    }
    float4* o4 = (float4*)(out + (size_t)tg*OUT_ + o0);
    o4[0] = r0; o4[1] = r1;
}

// ---------------- launch ----------------
extern "C" void kernel_launch(void* const* d_in, const int* in_sizes, int n_in,
                              void* d_out, int out_size) {
    const float* x  = (const float*)d_in[0];
    const float* fw = (const float*)d_in[1];
    const float* fb = (const float*)d_in[2];
    const float* vw = (const float*)d_in[3];
    const float* vb = (const float*)d_in[4];
    const float* pw = (const float*)d_in[5];
    const float* pb = (const float*)d_in[6];
    const float* sa = (const float*)d_in[7];
    const float* sb = (const float*)d_in[8];
    float* out = (float*)d_out;

    k_pool<<<B_*M_, 256>>>(x);
    k_cent<<<B_*M_, 256>>>(fw, fb, vw, vb);
    k_warm<<<1, 32>>>();
    k_featsim<<<NT_/128, 256>>>(x, fw, fb, sa, sb);
    k_xs<<<B_*NQ_, 256>>>(x);
    k_vagg<<<BH_*M_, 256>>>(vw, vb, pw);
    k_out<<<NT_/8, 256>>>(pb, out);
}